// round 7
// baseline (speedup 1.0000x reference)
#include <cuda_runtime.h>
#include <cstdint>
#include <math.h>

#define HH 12
#define NP 196
#define FF 8
#define DIMM 768
#define D3 192
#define BB 8
#define SS 1569
#define PP 195
#define C3 2304
#define SCALE_INV (1.0f/96.0f)

#define M1PAD 12672   // ceil(8*1569/128)*128
#define M2PAD 1664

// ---------------- scratch (device globals; zero-initialized) ----------------
__device__ float g_xq[BB*SS*C3];
__device__ float g_xk[BB*SS*C3];
__device__ float g_xv[BB*SS*C3];
__device__ float g_t1[BB*PP*C3];
__device__ float g_ti[BB*PP*DIMM];
__device__ float g_q2[BB*PP*C3];
__device__ float g_k2[BB*PP*C3];
__device__ float g_v2[BB*PP*C3];
__device__ float g_cls[BB*C3];
__device__ float g_t2[BB*FF*C3];
__device__ float g_rows[BB*9*DIMM];
// int8 two-digit buffers (A side, padded rows)
__device__ int8_t g_xD1[M1PAD*DIMM],  g_xD0[M1PAD*DIMM];   __device__ float g_sx[M1PAD];
__device__ int8_t g_t1D1[M2PAD*C3],   g_t1D0[M2PAD*C3];    __device__ float g_st1[M2PAD];
__device__ int8_t g_tiD1[M2PAD*DIMM], g_tiD0[M2PAD*DIMM];  __device__ float g_sti[M2PAD];
// weights: transposed [N,K] two-digit int8 + per-row scale
__device__ int8_t g_Wq1[C3*DIMM], g_Wq0[C3*DIMM];  __device__ float g_sWq[C3];
__device__ int8_t g_Wk1[C3*DIMM], g_Wk0[C3*DIMM];  __device__ float g_sWk[C3];
__device__ int8_t g_Wv1[C3*DIMM], g_Wv0[C3*DIMM];  __device__ float g_sWv[C3];
__device__ int8_t g_Wt1[DIMM*C3], g_Wt0[DIMM*C3];  __device__ float g_sWt[DIMM];
__device__ float g_WT[C3*DIMM];   // fp32 transpose scratch (reused)

// ---------------- helpers ----------------------------------------------------
__device__ __forceinline__ uint32_t smem_u32(const void* p) {
    uint32_t a;
    asm("{ .reg .u64 t; cvta.to.shared.u64 t, %1; cvt.u32.u64 %0, t; }" : "=r"(a) : "l"(p));
    return a;
}
#define CP_ASYNC16(dst_u32, src_ptr) \
    asm volatile("cp.async.cg.shared.global [%0], [%1], 16;" :: "r"(dst_u32), "l"(src_ptr))
#define CP_COMMIT() asm volatile("cp.async.commit_group;" ::: "memory")
#define CP_WAIT1()  asm volatile("cp.async.wait_group 1;" ::: "memory")

__device__ __forceinline__ void ldsm_x4(uint32_t addr, uint32_t& r0, uint32_t& r1,
                                        uint32_t& r2, uint32_t& r3) {
    asm volatile("ldmatrix.sync.aligned.m8n8.x4.shared.b16 {%0,%1,%2,%3}, [%4];"
                 : "=r"(r0), "=r"(r1), "=r"(r2), "=r"(r3) : "r"(addr));
}
__device__ __forceinline__ void imma(int* c, uint32_t a0, uint32_t a1, uint32_t a2, uint32_t a3,
                                     uint32_t b0, uint32_t b1) {
    asm volatile("mma.sync.aligned.m16n8k32.row.col.s32.s8.s8.s32 "
                 "{%0,%1,%2,%3}, {%4,%5,%6,%7}, {%8,%9}, {%0,%1,%2,%3};"
                 : "+r"(c[0]), "+r"(c[1]), "+r"(c[2]), "+r"(c[3])
                 : "r"(a0), "r"(a1), "r"(a2), "r"(a3), "r"(b0), "r"(b1));
}

// ---------------- fp32 transpose [K,N] -> [N,K] ------------------------------
__global__ void transpose_k(const float* __restrict__ in, float* __restrict__ out,
                            int K, int N) {
    __shared__ float t[32][33];
    const int n0 = blockIdx.x * 32, k0 = blockIdx.y * 32;
    const int tx = threadIdx.x & 31, ty = threadIdx.x >> 5;
#pragma unroll
    for (int i = 0; i < 32; i += 8)
        t[ty + i][tx] = in[(size_t)(k0 + ty + i) * N + n0 + tx];
    __syncthreads();
#pragma unroll
    for (int i = 0; i < 32; i += 8)
        out[(size_t)(n0 + ty + i) * K + k0 + tx] = t[tx][ty + i];
}

// ---------------- row quantization: fp32 row -> 2-digit int8 + scale --------
__global__ void quant_rows(const float* __restrict__ in, int8_t* __restrict__ d1,
                           int8_t* __restrict__ d0, float* __restrict__ sc, int K) {
    const int row = blockIdx.x;
    const int tid = threadIdx.x;
    __shared__ float red[8];
    const float* r = in + (size_t)row * K;
    float m = 0.f;
    for (int k = tid; k < K; k += 256) m = fmaxf(m, fabsf(r[k]));
#pragma unroll
    for (int off = 16; off; off >>= 1) m = fmaxf(m, __shfl_xor_sync(0xffffffffu, m, off));
    if ((tid & 31) == 0) red[tid >> 5] = m;
    __syncthreads();
    if (tid < 8) {
        float v = red[tid];
#pragma unroll
        for (int off = 4; off; off >>= 1) v = fmaxf(v, __shfl_xor_sync(0xffu, v, off));
        if (tid == 0) red[0] = v;
    }
    __syncthreads();
    m = red[0];
    const float s   = (m > 0.f) ? m / 16256.f : 1.f;
    const float inv = (m > 0.f) ? 16256.f / m : 0.f;
    if (tid == 0) sc[row] = s;
    for (int k = tid; k < K; k += 256) {
        int qi = __float2int_rn(r[k] * inv);
        int a1 = (qi >= 0) ? ((qi + 64) >> 7) : -(((-qi) + 64) >> 7);
        int a0 = qi - (a1 << 7);
        d1[(size_t)row * K + k] = (int8_t)a1;
        d0[(size_t)row * K + k] = (int8_t)a0;
    }
}

// ================= int8 IMMA GEMM (2-digit, 3-pass) ==========================
// C(MxN) = sA[m]*sB[n]*(16384*P11 + 128*(P10+P01)) + bias
// CTA 64x128, warp tile 32x32 (2x4 warps), BK=32, 2-stage cp.async, 2 CTA/SM.
#define LDI 48
#define IT_A (64 * LDI)               // 3072 B per A digit tile
#define IT_B (128 * LDI)              // 6144 B per B digit tile
#define ISTAGE (2 * IT_A + 2 * IT_B)  // 18432 B per stage

__global__ void __launch_bounds__(256, 2)
gemm_i8(const int8_t* __restrict__ A1, const int8_t* __restrict__ A0, const float* __restrict__ sA,
        const int8_t* __restrict__ B1, const int8_t* __restrict__ B0, const float* __restrict__ sB,
        const float* __restrict__ bias, float* __restrict__ C, int M, int N, int K) {
    extern __shared__ char smem[];
    const uint32_t smem_b = smem_u32(smem);
    const int tid = threadIdx.x, lane = tid & 31, wid = tid >> 5;
    const int wm = wid >> 2, wn = wid & 3;
    const int rowA0 = blockIdx.y * 64;
    const int n0 = blockIdx.x * 128;
    const int nch = K >> 5;

    // cp.async coordinates: A 256 slots (1/thread), B 512 slots (2/thread)
    const int ad = tid >> 7, ar = (tid >> 1) & 63, ah = tid & 1;
    const int8_t* srcA = (ad ? A0 : A1) + (size_t)(rowA0 + ar) * K + ah * 16;
    const uint32_t dstA = smem_b + ad * IT_A + ar * LDI + ah * 16;
    const int br = (tid >> 1) & 127, bh = tid & 1;
    const int8_t* srcB1 = B1 + (size_t)(n0 + br) * K + bh * 16;
    const int8_t* srcB0 = B0 + (size_t)(n0 + br) * K + bh * 16;
    const uint32_t dstB1 = smem_b + 2 * IT_A + br * LDI + bh * 16;
    const uint32_t dstB0 = smem_b + 2 * IT_A + IT_B + br * LDI + bh * 16;

    auto issue = [&](int c, int buf) {
        const int k0 = c << 5;
        const uint32_t sb = buf * ISTAGE;
        CP_ASYNC16(dstA + sb, srcA + k0);
        CP_ASYNC16(dstB1 + sb, srcB1 + k0);
        CP_ASYNC16(dstB0 + sb, srcB0 + k0);
    };

    int accH[2][4][4], accL[2][4][4];
#pragma unroll
    for (int mt = 0; mt < 2; mt++)
#pragma unroll
        for (int nt = 0; nt < 4; nt++)
#pragma unroll
            for (int e = 0; e < 4; e++) { accH[mt][nt][e] = 0; accL[mt][nt][e] = 0; }

    const int lrow = lane & 15, lseg = lane >> 4;

    issue(0, 0); CP_COMMIT();
    for (int c = 0; c < nch; c++) {
        if (c + 1 < nch) issue(c + 1, (c + 1) & 1);
        CP_COMMIT(); CP_WAIT1(); __syncthreads();
        const uint32_t st = smem_b + (c & 1) * ISTAGE;

        uint32_t a1r[2][4], a0r[2][4];
#pragma unroll
        for (int mt = 0; mt < 2; mt++) {
            const uint32_t arow = (uint32_t)((wm * 32 + mt * 16 + lrow) * LDI + lseg * 16);
            ldsm_x4(st + arow, a1r[mt][0], a1r[mt][1], a1r[mt][2], a1r[mt][3]);
            ldsm_x4(st + IT_A + arow, a0r[mt][0], a0r[mt][1], a0r[mt][2], a0r[mt][3]);
        }
#pragma unroll
        for (int half = 0; half < 2; half++) {
            const uint32_t brow = (uint32_t)((wn * 32 + half * 16 + lrow) * LDI + lseg * 16);
            uint32_t p0, p1, p2, p3, q0, q1, q2, q3;
            ldsm_x4(st + 2 * IT_A + brow, p0, p1, p2, p3);            // B1: even/odd ntile
            ldsm_x4(st + 2 * IT_A + IT_B + brow, q0, q1, q2, q3);     // B0
            const int ne = half * 2, no = half * 2 + 1;
#pragma unroll
            for (int mt = 0; mt < 2; mt++) {
                imma(accH[mt][ne], a1r[mt][0], a1r[mt][1], a1r[mt][2], a1r[mt][3], p0, p2);
                imma(accH[mt][no], a1r[mt][0], a1r[mt][1], a1r[mt][2], a1r[mt][3], p1, p3);
                imma(accL[mt][ne], a1r[mt][0], a1r[mt][1], a1r[mt][2], a1r[mt][3], q0, q2);
                imma(accL[mt][no], a1r[mt][0], a1r[mt][1], a1r[mt][2], a1r[mt][3], q1, q3);
                imma(accL[mt][ne], a0r[mt][0], a0r[mt][1], a0r[mt][2], a0r[mt][3], p0, p2);
                imma(accL[mt][no], a0r[mt][0], a0r[mt][1], a0r[mt][2], a0r[mt][3], p1, p3);
            }
        }
        __syncthreads();
    }

    // register-direct epilogue
#pragma unroll
    for (int mt = 0; mt < 2; mt++) {
        const int gr0 = rowA0 + wm * 32 + mt * 16 + (lane >> 2);
#pragma unroll
        for (int nt = 0; nt < 4; nt++) {
            const int gc = n0 + wn * 32 + nt * 8 + 2 * (lane & 3);
            const float sb0 = sB[gc], sb1 = sB[gc + 1];
            const float bb0 = bias[gc], bb1 = bias[gc + 1];
            if (gr0 < M) {
                const float sa = sA[gr0];
                float v0 = sa * sb0 * (16384.f * (float)accH[mt][nt][0] + 128.f * (float)accL[mt][nt][0]) + bb0;
                float v1 = sa * sb1 * (16384.f * (float)accH[mt][nt][1] + 128.f * (float)accL[mt][nt][1]) + bb1;
                *(float2*)(C + (size_t)gr0 * N + gc) = make_float2(v0, v1);
            }
            if (gr0 + 8 < M) {
                const float sa = sA[gr0 + 8];
                float v0 = sa * sb0 * (16384.f * (float)accH[mt][nt][2] + 128.f * (float)accL[mt][nt][2]) + bb0;
                float v1 = sa * sb1 * (16384.f * (float)accH[mt][nt][3] + 128.f * (float)accL[mt][nt][3]) + bb1;
                *(float2*)(C + (size_t)(gr0 + 8) * N + gc) = make_float2(v0, v1);
            }
        }
    }
}

// ---------------- inter_cls ---------------------------------------------------
__global__ void inter_cls_kernel() {
    __shared__ float sc[SS];
    __shared__ float red[256];
    __shared__ float part[8 * D3];
    const int h = blockIdx.x, b = blockIdx.y;
    const int tid = threadIdx.x, lane = tid & 31, wid = tid >> 5;
    const float* baseq = g_xq + (size_t)b * SS * C3 + h * D3;
    const float* basek = g_xk + (size_t)b * SS * C3 + h * D3;
    const float* basev = g_xv + (size_t)b * SS * C3 + h * D3;

    float qv[6];
#pragma unroll
    for (int i = 0; i < 6; i++) qv[i] = baseq[lane + 32 * i];

    for (int t = wid; t < SS; t += 8) {
        const float* kr = basek + (size_t)t * C3;
        float p = 0.f;
#pragma unroll
        for (int i = 0; i < 6; i++) p += qv[i] * kr[lane + 32 * i];
#pragma unroll
        for (int off = 16; off; off >>= 1) p += __shfl_xor_sync(0xffffffffu, p, off);
        if (lane == 0) sc[t] = p * SCALE_INV;
    }
    __syncthreads();

    float m = -1e30f;
    for (int t = tid; t < SS; t += 256) m = fmaxf(m, sc[t]);
    red[tid] = m; __syncthreads();
    for (int s = 128; s; s >>= 1) { if (tid < s) red[tid] = fmaxf(red[tid], red[tid + s]); __syncthreads(); }
    m = red[0]; __syncthreads();

    float z = 0.f;
    for (int t = tid; t < SS; t += 256) { float e = expf(sc[t] - m); sc[t] = e; z += e; }
    red[tid] = z; __syncthreads();
    for (int s = 128; s; s >>= 1) { if (tid < s) red[tid] += red[tid + s]; __syncthreads(); }
    const float invZ = 1.f / red[0];
    __syncthreads();

    float a[6] = {0.f, 0.f, 0.f, 0.f, 0.f, 0.f};
    for (int t = wid; t < SS; t += 8) {
        const float p = sc[t];
        const float* vr = basev + (size_t)t * C3;
#pragma unroll
        for (int i = 0; i < 6; i++) a[i] += p * vr[lane + 32 * i];
    }
#pragma unroll
    for (int i = 0; i < 6; i++) part[wid * D3 + lane + 32 * i] = a[i];
    __syncthreads();
    if (tid < D3) {
        float s = 0.f;
#pragma unroll
        for (int w = 0; w < 8; w++) s += part[w * D3 + tid];
        g_cls[b * C3 + h * D3 + tid] = s * invZ;
    }
}

// ---------------- temporal attention ------------------------------------------
__global__ void temporal_kernel() {
    __shared__ float qs[8 * 193];
    __shared__ float ks[8 * 193];
    __shared__ float sc[8 * 9];
    __shared__ float cw[8];
    const int p = blockIdx.x, h = blockIdx.y, b = blockIdx.z;
    const int tid = threadIdx.x;
    const size_t bb = (size_t)b * SS * C3;

    for (int e = tid; e < 8 * D3; e += 192) {
        int f = e / D3, j = e - f * D3;
        int tok = f * NP + p + 2;
        qs[f * 193 + j] = g_xq[bb + (size_t)tok * C3 + h * D3 + j];
        ks[f * 193 + j] = g_xv[bb + (size_t)tok * C3 + h * D3 + j];
    }
    __syncthreads();

    if (tid < 64) {
        int f = tid >> 3, g = tid & 7;
        float s = 0.f;
        for (int j = 0; j < D3; j++) s += qs[f * 193 + j] * ks[g * 193 + j];
        sc[f * 9 + g] = s * SCALE_INV;
    }
    __syncthreads();

    if (tid < 8) {
        int f = tid;
        float mx = -1e30f;
        for (int g = 0; g < 8; g++) mx = fmaxf(mx, sc[f * 9 + g]);
        float z = 0.f;
        for (int g = 0; g < 8; g++) { float e = expf(sc[f * 9 + g] - mx); sc[f * 9 + g] = e; z += e; }
        float inv = 1.f / z;
        for (int g = 0; g < 8; g++) sc[f * 9 + g] *= inv;
    }
    __syncthreads();
    if (tid < 8) {
        int g = tid;
        float s = 0.f;
        for (int f = 0; f < 8; f++) s += sc[f * 9 + g];
        cw[g] = s;
    }
    __syncthreads();

    {
        int d = tid;
        float acc = 0.f;
#pragma unroll
        for (int g = 0; g < 8; g++) {
            int tok = g * NP + p + 2;
            acc += cw[g] * g_xk[bb + (size_t)tok * C3 + h * D3 + d];
        }
        g_t1[((size_t)b * PP + p) * C3 + h * D3 + d] = acc;
    }
}

// ---------------- output-stage attention ---------------------------------------
__global__ void out_attn_kernel(int xi_base, int nk) {
    extern __shared__ float sm[];
    float* Kb = sm;
    float* qb = sm + nk * 193;
    float* w  = qb + 8 * D3;
    const int xi = xi_base + blockIdx.x;
    const int h = blockIdx.y, b = blockIdx.z;
    const int tid = threadIdx.x, lane = tid & 31, wid = tid >> 5;
    const size_t rbase = (size_t)b * PP * C3 + h * D3;

    for (int e = tid; e < nk * D3; e += 256) {
        int r = e / D3, j = e - r * D3;
        int kp = (nk == 196) ? (r % PP) : (xi + r);
        Kb[r * 193 + j] = g_k2[rbase + (size_t)kp * C3 + j];
    }
    for (int k = tid; k < nk; k += 256) w[k] = 0.f;
    __syncthreads();

    for (int q = wid; q < 196; q += 8) {
        int qp = (xi + q) % PP;
        for (int j = lane; j < D3; j += 32)
            qb[wid * D3 + j] = g_q2[rbase + (size_t)qp * C3 + j];
        __syncwarp();

        float s[7];
        int cnt = 0;
        for (int k = lane; k < nk; k += 32) {
            float d = 0.f;
            const float* kr = Kb + k * 193;
            const float* qr = qb + wid * D3;
            for (int j = 0; j < D3; j++) d += qr[j] * kr[j];
            s[cnt++] = d * SCALE_INV;
        }
        float mx = -1e30f;
        for (int c = 0; c < cnt; c++) mx = fmaxf(mx, s[c]);
#pragma unroll
        for (int off = 16; off; off >>= 1) mx = fmaxf(mx, __shfl_xor_sync(0xffffffffu, mx, off));
        float z = 0.f;
        for (int c = 0; c < cnt; c++) { float e = expf(s[c] - mx); s[c] = e; z += e; }
#pragma unroll
        for (int off = 16; off; off >>= 1) z += __shfl_xor_sync(0xffffffffu, z, off);
        float inv = 1.f / z;
        int c = 0;
        for (int k = lane; k < nk; k += 32, c++) atomicAdd(&w[k], s[c] * inv);
        __syncwarp();
    }
    __syncthreads();

    if (tid < D3) {
        float acc = 0.f;
        for (int k = 0; k < nk; k++) {
            int kp = (nk == 196) ? (k % PP) : (xi + k);
            acc += w[k] * g_v2[rbase + (size_t)kp * C3 + tid];
        }
        g_t2[((size_t)b * FF + xi) * C3 + h * D3 + tid] = acc;
    }
}

// ---------------- final 9 rows per batch ----------------------------------------
__global__ void final_rows_kernel(const float* __restrict__ Wf, const float* __restrict__ bf) {
    extern __shared__ float As[];
    const int cb = blockIdx.x, b = blockIdx.y;
    const int tid = threadIdx.x;
    for (int e = tid; e < 9 * C3; e += 192) {
        int r = e / C3, k = e - r * C3;
        As[e] = (r == 0) ? g_cls[b * C3 + k] : g_t2[((size_t)b * FF + (r - 1)) * C3 + k];
    }
    __syncthreads();
    const int c = cb * 192 + tid;
    float acc[9];
#pragma unroll
    for (int r = 0; r < 9; r++) acc[r] = 0.f;
    for (int k = 0; k < C3; k++) {
        float wv = Wf[(size_t)k * DIMM + c];
#pragma unroll
        for (int r = 0; r < 9; r++) acc[r] += As[r * C3 + k] * wv;
    }
    float bv = bf[c];
#pragma unroll
    for (int r = 0; r < 9; r++)
        g_rows[((size_t)b * 9 + r) * DIMM + c] = acc[r] + bv;
}

// ---------------- broadcast -> output --------------------------------------------
__global__ void bcast_kernel(float* __restrict__ out) {
    size_t i4 = (size_t)blockIdx.x * blockDim.x + threadIdx.x;
    const size_t total4 = (size_t)BB * SS * DIMM / 4;
    if (i4 >= total4) return;
    size_t idx = i4 * 4;
    int c = idx % DIMM;
    size_t rs = idx / DIMM;
    int s = rs % SS;
    int b = rs / SS;
    int r = (s == 0) ? 0 : 1 + ((s - 1) & 7);
    ((float4*)out)[i4] = *(const float4*)(g_rows + ((size_t)b * 9 + r) * DIMM + c);
}

// ---------------- launch ----------------------------------------------------------
extern "C" void kernel_launch(void* const* d_in, const int* in_sizes, int n_in,
                              void* d_out, int out_size) {
    const float* x  = (const float*)d_in[0];
    const float* Wq = (const float*)d_in[1];
    const float* bq = (const float*)d_in[2];
    const float* Wk = (const float*)d_in[3];
    const float* bk = (const float*)d_in[4];
    const float* Wv = (const float*)d_in[5];
    const float* bv = (const float*)d_in[6];
    const float* Wt = (const float*)d_in[7];
    const float* bt = (const float*)d_in[8];
    const float* Wf = (const float*)d_in[9];
    const float* bf = (const float*)d_in[10];
    float* out = (float*)d_out;

    float *p_xq, *p_xk, *p_xv, *p_t1, *p_ti, *p_q2, *p_k2, *p_v2, *p_WT;
    cudaGetSymbolAddress((void**)&p_xq, g_xq);
    cudaGetSymbolAddress((void**)&p_xk, g_xk);
    cudaGetSymbolAddress((void**)&p_xv, g_xv);
    cudaGetSymbolAddress((void**)&p_t1, g_t1);
    cudaGetSymbolAddress((void**)&p_ti, g_ti);
    cudaGetSymbolAddress((void**)&p_q2, g_q2);
    cudaGetSymbolAddress((void**)&p_k2, g_k2);
    cudaGetSymbolAddress((void**)&p_v2, g_v2);
    cudaGetSymbolAddress((void**)&p_WT, g_WT);
    int8_t *p_xD1, *p_xD0, *p_t1D1, *p_t1D0, *p_tiD1, *p_tiD0;
    int8_t *p_Wq1, *p_Wq0, *p_Wk1, *p_Wk0, *p_Wv1, *p_Wv0, *p_Wt1, *p_Wt0;
    float *p_sx, *p_st1, *p_sti, *p_sWq, *p_sWk, *p_sWv, *p_sWt;
    cudaGetSymbolAddress((void**)&p_xD1, g_xD1);   cudaGetSymbolAddress((void**)&p_xD0, g_xD0);
    cudaGetSymbolAddress((void**)&p_t1D1, g_t1D1); cudaGetSymbolAddress((void**)&p_t1D0, g_t1D0);
    cudaGetSymbolAddress((void**)&p_tiD1, g_tiD1); cudaGetSymbolAddress((void**)&p_tiD0, g_tiD0);
    cudaGetSymbolAddress((void**)&p_Wq1, g_Wq1);   cudaGetSymbolAddress((void**)&p_Wq0, g_Wq0);
    cudaGetSymbolAddress((void**)&p_Wk1, g_Wk1);   cudaGetSymbolAddress((void**)&p_Wk0, g_Wk0);
    cudaGetSymbolAddress((void**)&p_Wv1, g_Wv1);   cudaGetSymbolAddress((void**)&p_Wv0, g_Wv0);
    cudaGetSymbolAddress((void**)&p_Wt1, g_Wt1);   cudaGetSymbolAddress((void**)&p_Wt0, g_Wt0);
    cudaGetSymbolAddress((void**)&p_sx, g_sx);
    cudaGetSymbolAddress((void**)&p_st1, g_st1);
    cudaGetSymbolAddress((void**)&p_sti, g_sti);
    cudaGetSymbolAddress((void**)&p_sWq, g_sWq);
    cudaGetSymbolAddress((void**)&p_sWk, g_sWk);
    cudaGetSymbolAddress((void**)&p_sWv, g_sWv);
    cudaGetSymbolAddress((void**)&p_sWt, g_sWt);

    const size_t I8_SMEM = 2 * (size_t)ISTAGE;  // 36864
    cudaFuncSetAttribute(gemm_i8, cudaFuncAttributeMaxDynamicSharedMemorySize, (int)I8_SMEM);
    cudaFuncSetAttribute(out_attn_kernel, cudaFuncAttributeMaxDynamicSharedMemorySize, 160000);
    cudaFuncSetAttribute(final_rows_kernel, cudaFuncAttributeMaxDynamicSharedMemorySize, 9 * C3 * 4);

    // weights: transpose -> quantize (sequential reuse of g_WT)
    transpose_k<<<dim3(C3 / 32, DIMM / 32), 256>>>(Wq, p_WT, DIMM, C3);
    quant_rows<<<C3, 256>>>(p_WT, p_Wq1, p_Wq0, p_sWq, DIMM);
    transpose_k<<<dim3(C3 / 32, DIMM / 32), 256>>>(Wk, p_WT, DIMM, C3);
    quant_rows<<<C3, 256>>>(p_WT, p_Wk1, p_Wk0, p_sWk, DIMM);
    transpose_k<<<dim3(C3 / 32, DIMM / 32), 256>>>(Wv, p_WT, DIMM, C3);
    quant_rows<<<C3, 256>>>(p_WT, p_Wv1, p_Wv0, p_sWv, DIMM);
    transpose_k<<<dim3(DIMM / 32, C3 / 32), 256>>>(Wt, p_WT, C3, DIMM);
    quant_rows<<<DIMM, 256>>>(p_WT, p_Wt1, p_Wt0, p_sWt, C3);

    const int M1 = BB * SS;   // 12552
    quant_rows<<<M1, 256>>>(x, p_xD1, p_xD0, p_sx, DIMM);
    {
        dim3 grid(C3 / 128, M1PAD / 64);
        gemm_i8<<<grid, 256, I8_SMEM>>>(p_xD1, p_xD0, p_sx, p_Wq1, p_Wq0, p_sWq, bq, p_xq, M1, C3, DIMM);
        gemm_i8<<<grid, 256, I8_SMEM>>>(p_xD1, p_xD0, p_sx, p_Wk1, p_Wk0, p_sWk, bk, p_xk, M1, C3, DIMM);
        gemm_i8<<<grid, 256, I8_SMEM>>>(p_xD1, p_xD0, p_sx, p_Wv1, p_Wv0, p_sWv, bv, p_xv, M1, C3, DIMM);
    }
    inter_cls_kernel<<<dim3(HH, BB), 256>>>();
    temporal_kernel<<<dim3(PP, HH, BB), 192>>>();

    const int M2 = BB * PP;   // 1560
    quant_rows<<<M2, 256>>>(p_t1, p_t1D1, p_t1D0, p_st1, C3);
    {
        dim3 grid(DIMM / 128, M2PAD / 64);
        gemm_i8<<<grid, 256, I8_SMEM>>>(p_t1D1, p_t1D0, p_st1, p_Wt1, p_Wt0, p_sWt, bt, p_ti, M2, DIMM, C3);
    }
    quant_rows<<<M2, 256>>>(p_ti, p_tiD1, p_tiD0, p_sti, DIMM);
    {
        dim3 grid(C3 / 128, M2PAD / 64);
        gemm_i8<<<grid, 256, I8_SMEM>>>(p_tiD1, p_tiD0, p_sti, p_Wq1, p_Wq0, p_sWq, bq, p_q2, M2, C3, DIMM);
        gemm_i8<<<grid, 256, I8_SMEM>>>(p_tiD1, p_tiD0, p_sti, p_Wv1, p_Wv0, p_sWv, bv, p_k2, M2, C3, DIMM);
        gemm_i8<<<grid, 256, I8_SMEM>>>(p_tiD1, p_tiD0, p_sti, p_Wk1, p_Wk0, p_sWk, bk, p_v2, M2, C3, DIMM);
    }
    {
        size_t smA = (size_t)(196 * 193 + 8 * D3 + 196) * 4;
        out_attn_kernel<<<dim3(1, HH, BB), 256, smA>>>(0, 196);
        size_t smB = (size_t)(8 * 193 + 8 * D3 + 8) * 4;
        out_attn_kernel<<<dim3(7, HH, BB), 256, smB>>>(1, 8);
    }
    final_rows_kernel<<<dim3(4, BB), 192, (size_t)9 * C3 * 4>>>(Wf, bf);
    {
        const size_t total4 = (size_t)BB * SS * DIMM / 4;
        bcast_kernel<<<(unsigned)((total4 + 255) / 256), 256>>>(out);
    }
}

// round 8
// speedup vs baseline: 1.6352x; 1.6352x over previous
#include <cuda_runtime.h>
#include <cuda_bf16.h>
#include <mma.h>
#include <cstdint>
#include <math.h>

using namespace nvcuda;

#define HH 12
#define NP 196
#define FF 8
#define DIMM 768
#define D3 192
#define BB 8
#define SS 1569
#define PP 195
#define C3 2304
#define C3X 6912            // fused QKV row width
#define OQ 0                // x@Wq offset
#define OK 2304             // x@Wk offset
#define OV 4608             // x@Wv offset
#define SCALE_INV (1.0f/96.0f)

#define M1PAD 12672   // ceil(8*1569/128)*128
#define M2PAD 1664    // ceil(8*195/128)*128

// ---------------- scratch (device globals; zero-initialized) ----------------
__device__ float g_qkv[BB*SS*C3X];     // fused [x@Wq | x@Wk | x@Wv]
__device__ float g_t1[BB*PP*C3];
__device__ float g_ti[BB*PP*DIMM];
__device__ float g_q2kv[BB*PP*C3X];    // fused [ti@Wq | ti@Wk | ti@Wv]
__device__ float g_cls[BB*C3];
__device__ float g_t2[BB*FF*C3];
__device__ float g_rows[BB*9*DIMM];
__device__ float g_bqkv[C3X];          // fused bias
// bf16 hi/lo split buffers (A-side, padded rows)
__device__ __nv_bfloat16 g_xhi[M1PAD*DIMM],  g_xlo[M1PAD*DIMM];
__device__ __nv_bfloat16 g_t1hi[M2PAD*C3],   g_t1lo[M2PAD*C3];
__device__ __nv_bfloat16 g_tihi[M2PAD*DIMM], g_tilo[M2PAD*DIMM];
// fused transposed weights [6912, 768] bf16 hi/lo + Wt [768, 2304]
__device__ __nv_bfloat16 g_Whi[C3X*DIMM], g_Wlo[C3X*DIMM];
__device__ __nv_bfloat16 g_WtThi[DIMM*C3], g_WtTlo[DIMM*C3];

// ---------------- cp.async helpers ------------------------------------------
__device__ __forceinline__ uint32_t smem_u32(const void* p) {
    uint32_t a;
    asm("{ .reg .u64 t; cvta.to.shared.u64 t, %1; cvt.u32.u64 %0, t; }" : "=r"(a) : "l"(p));
    return a;
}
#define CP_ASYNC16(dst_u32, src_ptr) \
    asm volatile("cp.async.cg.shared.global [%0], [%1], 16;" :: "r"(dst_u32), "l"(src_ptr))
#define CP_COMMIT() asm volatile("cp.async.commit_group;" ::: "memory")
#define CP_WAIT1()  asm volatile("cp.async.wait_group 1;" ::: "memory")

// ---------------- split: fp32 -> bf16 hi + bf16 lo --------------------------
__global__ void split_f32(const float* __restrict__ in, __nv_bfloat16* __restrict__ hi,
                          __nv_bfloat16* __restrict__ lo, int n4) {
    int i = blockIdx.x * blockDim.x + threadIdx.x;
    if (i >= n4) return;
    float4 v = ((const float4*)in)[i];
    __nv_bfloat16 h0 = __float2bfloat16(v.x), h1 = __float2bfloat16(v.y);
    __nv_bfloat16 h2 = __float2bfloat16(v.z), h3 = __float2bfloat16(v.w);
    __nv_bfloat162 lo01(__float2bfloat16(v.x - __bfloat162float(h0)),
                        __float2bfloat16(v.y - __bfloat162float(h1)));
    __nv_bfloat162 lo23(__float2bfloat16(v.z - __bfloat162float(h2)),
                        __float2bfloat16(v.w - __bfloat162float(h3)));
    ((__nv_bfloat162*)hi)[i * 2 + 0] = __nv_bfloat162(h0, h1);
    ((__nv_bfloat162*)hi)[i * 2 + 1] = __nv_bfloat162(h2, h3);
    ((__nv_bfloat162*)lo)[i * 2 + 0] = lo01;
    ((__nv_bfloat162*)lo)[i * 2 + 1] = lo23;
}

// ---------------- transpose + split: fp32 [K,N] -> bf16 hi/lo [N,K] ---------
__global__ void transpose_split(const float* __restrict__ in,
                                __nv_bfloat16* __restrict__ hi,
                                __nv_bfloat16* __restrict__ lo, int K, int N) {
    __shared__ float t[32][33];
    const int n0 = blockIdx.x * 32, k0 = blockIdx.y * 32;
    const int tx = threadIdx.x & 31, ty = threadIdx.x >> 5;
#pragma unroll
    for (int i = 0; i < 32; i += 8)
        t[ty + i][tx] = in[(size_t)(k0 + ty + i) * N + n0 + tx];
    __syncthreads();
#pragma unroll
    for (int i = 0; i < 32; i += 8) {
        float v = t[tx][ty + i];
        __nv_bfloat16 h = __float2bfloat16(v);
        hi[(size_t)(n0 + ty + i) * K + k0 + tx] = h;
        lo[(size_t)(n0 + ty + i) * K + k0 + tx] = __float2bfloat16(v - __bfloat162float(h));
    }
}

// ---------------- bias concat -------------------------------------------------
__global__ void concat_bias(const float* __restrict__ bq, const float* __restrict__ bk,
                            const float* __restrict__ bv, float* __restrict__ outb) {
    int i = blockIdx.x * blockDim.x + threadIdx.x;
    if (i >= C3X) return;
    outb[i] = (i < OK) ? bq[i] : (i < OV) ? bk[i - OK] : bv[i - OV];
}

// ================= bf16-split HMMA GEMM, 2-stage cp.async, 2 CTA/SM =========
// C(MxN) = [Ahi+Alo](MxK) @ [Bhi+Blo]([N,K])^T + bias, 3-pass fp32 accumulate.
#define LDT 40
#define TILE_B (128 * LDT * 2)        // 10240 bytes per bf16 tile
#define STAGE_B (4 * TILE_B)          // 40960 bytes per stage
#define NSTAGE 2

__global__ void __launch_bounds__(256, 2)
gemm_bs(const __nv_bfloat16* __restrict__ Ahi, const __nv_bfloat16* __restrict__ Alo,
        const __nv_bfloat16* __restrict__ Bhi, const __nv_bfloat16* __restrict__ Blo,
        const float* __restrict__ bias, float* __restrict__ C,
        int M, int N, int K) {
    extern __shared__ char smem[];
    const uint32_t smem_b = smem_u32(smem);
    const int tid = threadIdx.x;
    const int wid = tid >> 5;
    const int wm = wid & 3, wn = wid >> 2;
    const int rowA0 = blockIdx.y * 128;
    const int n0 = blockIdx.x * 128;
    const int nch = K >> 5;

    const int r_cp = tid >> 1;
    const int s_cp = (tid & 1) * 2;
    const __nv_bfloat16* srcs[4];
    srcs[0] = Ahi + (size_t)(rowA0 + r_cp) * K;
    srcs[1] = Alo + (size_t)(rowA0 + r_cp) * K;
    srcs[2] = Bhi + (size_t)(n0 + r_cp) * K;
    srcs[3] = Blo + (size_t)(n0 + r_cp) * K;
    const uint32_t dst_row = smem_b + r_cp * (LDT * 2);

    auto issue_stage = [&](int c, int buf) {
        const int k0 = c << 5;
        const uint32_t sb = buf * STAGE_B;
#pragma unroll
        for (int t = 0; t < 4; t++) {
            const __nv_bfloat16* src = srcs[t] + k0 + s_cp * 8;
            const uint32_t dst = dst_row + sb + t * TILE_B + s_cp * 16;
            CP_ASYNC16(dst, src);
            CP_ASYNC16(dst + 16, src + 8);
        }
    };

    wmma::fragment<wmma::accumulator, 16, 16, 16, float> acc[2][4];
#pragma unroll
    for (int i = 0; i < 2; i++)
#pragma unroll
        for (int j = 0; j < 4; j++) wmma::fill_fragment(acc[i][j], 0.f);

    issue_stage(0, 0);
    CP_COMMIT();

    for (int c = 0; c < nch; c++) {
        if (c + 1 < nch) issue_stage(c + 1, (c + 1) & 1);
        CP_COMMIT();
        CP_WAIT1();
        __syncthreads();

        const __nv_bfloat16* Ah = (const __nv_bfloat16*)(smem + (c & 1) * STAGE_B);
        const __nv_bfloat16* Al = Ah + 128 * LDT;
        const __nv_bfloat16* Bh = Al + 128 * LDT;
        const __nv_bfloat16* Bl = Bh + 128 * LDT;
#pragma unroll
        for (int kk = 0; kk < 32; kk += 16) {
            wmma::fragment<wmma::matrix_a, 16, 16, 16, __nv_bfloat16, wmma::row_major> ah[2], al[2];
#pragma unroll
            for (int i = 0; i < 2; i++) {
                wmma::load_matrix_sync(ah[i], Ah + (wm * 32 + i * 16) * LDT + kk, LDT);
                wmma::load_matrix_sync(al[i], Al + (wm * 32 + i * 16) * LDT + kk, LDT);
            }
#pragma unroll
            for (int j = 0; j < 4; j++) {
                {   // hi*hi and lo*hi with one live B fragment
                    wmma::fragment<wmma::matrix_b, 16, 16, 16, __nv_bfloat16, wmma::col_major> bh;
                    wmma::load_matrix_sync(bh, Bh + (wn * 64 + j * 16) * LDT + kk, LDT);
                    wmma::mma_sync(acc[0][j], ah[0], bh, acc[0][j]);
                    wmma::mma_sync(acc[1][j], ah[1], bh, acc[1][j]);
                    wmma::mma_sync(acc[0][j], al[0], bh, acc[0][j]);
                    wmma::mma_sync(acc[1][j], al[1], bh, acc[1][j]);
                }
                {   // hi*lo
                    wmma::fragment<wmma::matrix_b, 16, 16, 16, __nv_bfloat16, wmma::col_major> bl;
                    wmma::load_matrix_sync(bl, Bl + (wn * 64 + j * 16) * LDT + kk, LDT);
                    wmma::mma_sync(acc[0][j], ah[0], bl, acc[0][j]);
                    wmma::mma_sync(acc[1][j], ah[1], bl, acc[1][j]);
                }
            }
        }
        __syncthreads();
    }

    float* sC = (float*)smem;
#pragma unroll
    for (int i = 0; i < 2; i++)
#pragma unroll
        for (int j = 0; j < 4; j++)
            wmma::store_matrix_sync(sC + (wm * 32 + i * 16) * 128 + wn * 64 + j * 16,
                                    acc[i][j], 128, wmma::mem_row_major);
    __syncthreads();
#pragma unroll
    for (int i = 0; i < 16; i++) {
        const int f = i * 256 + tid;
        const int r = f >> 5, c4 = f & 31;
        const int gm = rowA0 + r;
        if (gm < M) {
            float4 v = *(float4*)(sC + r * 128 + c4 * 4);
            const int n = n0 + c4 * 4;
            v.x += bias[n + 0];
            v.y += bias[n + 1];
            v.z += bias[n + 2];
            v.w += bias[n + 3];
            *(float4*)(C + (size_t)gm * N + n) = v;
        }
    }
}

// ---------------- inter_cls (fused-buffer strides) ----------------------------
__global__ void inter_cls_kernel() {
    __shared__ float sc[SS];
    __shared__ float red[256];
    __shared__ float part[8 * D3];
    const int h = blockIdx.x, b = blockIdx.y;
    const int tid = threadIdx.x, lane = tid & 31, wid = tid >> 5;
    const float* baseq = g_qkv + (size_t)b * SS * C3X + OQ + h * D3;
    const float* basek = g_qkv + (size_t)b * SS * C3X + OK + h * D3;
    const float* basev = g_qkv + (size_t)b * SS * C3X + OV + h * D3;

    float qv[6];
#pragma unroll
    for (int i = 0; i < 6; i++) qv[i] = baseq[lane + 32 * i];

    for (int t = wid; t < SS; t += 8) {
        const float* kr = basek + (size_t)t * C3X;
        float p = 0.f;
#pragma unroll
        for (int i = 0; i < 6; i++) p += qv[i] * kr[lane + 32 * i];
#pragma unroll
        for (int off = 16; off; off >>= 1) p += __shfl_xor_sync(0xffffffffu, p, off);
        if (lane == 0) sc[t] = p * SCALE_INV;
    }
    __syncthreads();

    float m = -1e30f;
    for (int t = tid; t < SS; t += 256) m = fmaxf(m, sc[t]);
    red[tid] = m; __syncthreads();
    for (int s = 128; s; s >>= 1) { if (tid < s) red[tid] = fmaxf(red[tid], red[tid + s]); __syncthreads(); }
    m = red[0]; __syncthreads();

    float z = 0.f;
    for (int t = tid; t < SS; t += 256) { float e = expf(sc[t] - m); sc[t] = e; z += e; }
    red[tid] = z; __syncthreads();
    for (int s = 128; s; s >>= 1) { if (tid < s) red[tid] += red[tid + s]; __syncthreads(); }
    const float invZ = 1.f / red[0];
    __syncthreads();

    float a[6] = {0.f, 0.f, 0.f, 0.f, 0.f, 0.f};
    for (int t = wid; t < SS; t += 8) {
        const float p = sc[t];
        const float* vr = basev + (size_t)t * C3X;
#pragma unroll
        for (int i = 0; i < 6; i++) a[i] += p * vr[lane + 32 * i];
    }
#pragma unroll
    for (int i = 0; i < 6; i++) part[wid * D3 + lane + 32 * i] = a[i];
    __syncthreads();
    if (tid < D3) {
        float s = 0.f;
#pragma unroll
        for (int w = 0; w < 8; w++) s += part[w * D3 + tid];
        g_cls[b * C3 + h * D3 + tid] = s * invZ;
    }
}

// ---------------- temporal attention ------------------------------------------
__global__ void temporal_kernel() {
    __shared__ float qs[8 * 193];
    __shared__ float ks[8 * 193];
    __shared__ float sc[8 * 9];
    __shared__ float cw[8];
    const int p = blockIdx.x, h = blockIdx.y, b = blockIdx.z;
    const int tid = threadIdx.x;
    const size_t bb = (size_t)b * SS * C3X;

    for (int e = tid; e < 8 * D3; e += 192) {
        int f = e / D3, j = e - f * D3;
        int tok = f * NP + p + 2;
        qs[f * 193 + j] = g_qkv[bb + (size_t)tok * C3X + OQ + h * D3 + j];   // qm
        ks[f * 193 + j] = g_qkv[bb + (size_t)tok * C3X + OV + h * D3 + j];   // k5 = Wv proj
    }
    __syncthreads();

    if (tid < 64) {
        int f = tid >> 3, g = tid & 7;
        float s = 0.f;
        for (int j = 0; j < D3; j++) s += qs[f * 193 + j] * ks[g * 193 + j];
        sc[f * 9 + g] = s * SCALE_INV;
    }
    __syncthreads();

    if (tid < 8) {
        int f = tid;
        float mx = -1e30f;
        for (int g = 0; g < 8; g++) mx = fmaxf(mx, sc[f * 9 + g]);
        float z = 0.f;
        for (int g = 0; g < 8; g++) { float e = expf(sc[f * 9 + g] - mx); sc[f * 9 + g] = e; z += e; }
        float inv = 1.f / z;
        for (int g = 0; g < 8; g++) sc[f * 9 + g] *= inv;
    }
    __syncthreads();
    if (tid < 8) {
        int g = tid;
        float s = 0.f;
        for (int f = 0; f < 8; f++) s += sc[f * 9 + g];
        cw[g] = s;
    }
    __syncthreads();

    {
        int d = tid;
        float acc = 0.f;
#pragma unroll
        for (int g = 0; g < 8; g++) {
            int tok = g * NP + p + 2;
            acc += cw[g] * g_qkv[bb + (size_t)tok * C3X + OK + h * D3 + d];  // v5 = Wk proj
        }
        g_t1[((size_t)b * PP + p) * C3 + h * D3 + d] = acc;
    }
}

// ---------------- output-stage attention ---------------------------------------
__global__ void out_attn_kernel(int xi_base, int nk) {
    extern __shared__ float sm[];
    float* Kb = sm;
    float* qb = sm + nk * 193;
    float* w  = qb + 8 * D3;
    const int xi = xi_base + blockIdx.x;
    const int h = blockIdx.y, b = blockIdx.z;
    const int tid = threadIdx.x, lane = tid & 31, wid = tid >> 5;
    const size_t rbase = (size_t)b * PP * C3X + h * D3;

    for (int e = tid; e < nk * D3; e += 256) {
        int r = e / D3, j = e - r * D3;
        int kp = (nk == 196) ? (r % PP) : (xi + r);
        Kb[r * 193 + j] = g_q2kv[rbase + (size_t)kp * C3X + OV + j];   // k2 = ti@Wv
    }
    for (int k = tid; k < nk; k += 256) w[k] = 0.f;
    __syncthreads();

    for (int q = wid; q < 196; q += 8) {
        int qp = (xi + q) % PP;
        for (int j = lane; j < D3; j += 32)
            qb[wid * D3 + j] = g_q2kv[rbase + (size_t)qp * C3X + OQ + j];  // q2 = ti@Wq
        __syncwarp();

        float s[7];
        int cnt = 0;
        for (int k = lane; k < nk; k += 32) {
            float d = 0.f;
            const float* kr = Kb + k * 193;
            const float* qr = qb + wid * D3;
            for (int j = 0; j < D3; j++) d += qr[j] * kr[j];
            s[cnt++] = d * SCALE_INV;
        }
        float mx = -1e30f;
        for (int c = 0; c < cnt; c++) mx = fmaxf(mx, s[c]);
#pragma unroll
        for (int off = 16; off; off >>= 1) mx = fmaxf(mx, __shfl_xor_sync(0xffffffffu, mx, off));
        float z = 0.f;
        for (int c = 0; c < cnt; c++) { float e = expf(s[c] - mx); s[c] = e; z += e; }
#pragma unroll
        for (int off = 16; off; off >>= 1) z += __shfl_xor_sync(0xffffffffu, z, off);
        float inv = 1.f / z;
        int c = 0;
        for (int k = lane; k < nk; k += 32, c++) atomicAdd(&w[k], s[c] * inv);
        __syncwarp();
    }
    __syncthreads();

    if (tid < D3) {
        float acc = 0.f;
        for (int k = 0; k < nk; k++) {
            int kp = (nk == 196) ? (k % PP) : (xi + k);
            acc += w[k] * g_q2kv[rbase + (size_t)kp * C3X + OK + tid];   // v2 = ti@Wk
        }
        g_t2[((size_t)b * FF + xi) * C3 + h * D3 + tid] = acc;
    }
}

// ---------------- final 9 rows per batch ----------------------------------------
__global__ void final_rows_kernel(const float* __restrict__ Wf, const float* __restrict__ bf) {
    extern __shared__ float As[];
    const int cb = blockIdx.x, b = blockIdx.y;
    const int tid = threadIdx.x;
    for (int e = tid; e < 9 * C3; e += 192) {
        int r = e / C3, k = e - r * C3;
        As[e] = (r == 0) ? g_cls[b * C3 + k] : g_t2[((size_t)b * FF + (r - 1)) * C3 + k];
    }
    __syncthreads();
    const int c = cb * 192 + tid;
    float acc[9];
#pragma unroll
    for (int r = 0; r < 9; r++) acc[r] = 0.f;
    for (int k = 0; k < C3; k++) {
        float wv = Wf[(size_t)k * DIMM + c];
#pragma unroll
        for (int r = 0; r < 9; r++) acc[r] += As[r * C3 + k] * wv;
    }
    float bv = bf[c];
#pragma unroll
    for (int r = 0; r < 9; r++)
        g_rows[((size_t)b * 9 + r) * DIMM + c] = acc[r] + bv;
}

// ---------------- broadcast -> output --------------------------------------------
__global__ void bcast_kernel(float* __restrict__ out) {
    size_t i4 = (size_t)blockIdx.x * blockDim.x + threadIdx.x;
    const size_t total4 = (size_t)BB * SS * DIMM / 4;
    if (i4 >= total4) return;
    size_t idx = i4 * 4;
    int c = idx % DIMM;
    size_t rs = idx / DIMM;
    int s = rs % SS;
    int b = rs / SS;
    int r = (s == 0) ? 0 : 1 + ((s - 1) & 7);
    ((float4*)out)[i4] = *(const float4*)(g_rows + ((size_t)b * 9 + r) * DIMM + c);
}

// ---------------- launch ----------------------------------------------------------
extern "C" void kernel_launch(void* const* d_in, const int* in_sizes, int n_in,
                              void* d_out, int out_size) {
    const float* x  = (const float*)d_in[0];
    const float* Wq = (const float*)d_in[1];
    const float* bq = (const float*)d_in[2];
    const float* Wk = (const float*)d_in[3];
    const float* bk = (const float*)d_in[4];
    const float* Wv = (const float*)d_in[5];
    const float* bv = (const float*)d_in[6];
    const float* Wt = (const float*)d_in[7];
    const float* bt = (const float*)d_in[8];
    const float* Wf = (const float*)d_in[9];
    const float* bf = (const float*)d_in[10];
    float* out = (float*)d_out;

    float *p_qkv, *p_t1, *p_ti, *p_q2kv, *p_bqkv;
    cudaGetSymbolAddress((void**)&p_qkv, g_qkv);
    cudaGetSymbolAddress((void**)&p_t1, g_t1);
    cudaGetSymbolAddress((void**)&p_ti, g_ti);
    cudaGetSymbolAddress((void**)&p_q2kv, g_q2kv);
    cudaGetSymbolAddress((void**)&p_bqkv, g_bqkv);
    __nv_bfloat16 *p_xhi, *p_xlo, *p_t1hi, *p_t1lo, *p_tihi, *p_tilo;
    __nv_bfloat16 *p_Whi, *p_Wlo, *p_Wthi, *p_Wtlo;
    cudaGetSymbolAddress((void**)&p_xhi, g_xhi);
    cudaGetSymbolAddress((void**)&p_xlo, g_xlo);
    cudaGetSymbolAddress((void**)&p_t1hi, g_t1hi);
    cudaGetSymbolAddress((void**)&p_t1lo, g_t1lo);
    cudaGetSymbolAddress((void**)&p_tihi, g_tihi);
    cudaGetSymbolAddress((void**)&p_tilo, g_tilo);
    cudaGetSymbolAddress((void**)&p_Whi, g_Whi);
    cudaGetSymbolAddress((void**)&p_Wlo, g_Wlo);
    cudaGetSymbolAddress((void**)&p_Wthi, g_WtThi);
    cudaGetSymbolAddress((void**)&p_Wtlo, g_WtTlo);

    const size_t GEMM_SMEM = (size_t)NSTAGE * STAGE_B;  // 81920
    cudaFuncSetAttribute(gemm_bs, cudaFuncAttributeMaxDynamicSharedMemorySize, (int)GEMM_SMEM);
    cudaFuncSetAttribute(out_attn_kernel, cudaFuncAttributeMaxDynamicSharedMemorySize, 160000);
    cudaFuncSetAttribute(final_rows_kernel, cudaFuncAttributeMaxDynamicSharedMemorySize, 9 * C3 * 4);

    // fused weight transpose+split: [Wq|Wk|Wv] -> [6912, 768] hi/lo
    transpose_split<<<dim3(C3 / 32, DIMM / 32), 256>>>(Wq, p_Whi + (size_t)OQ * DIMM, p_Wlo + (size_t)OQ * DIMM, DIMM, C3);
    transpose_split<<<dim3(C3 / 32, DIMM / 32), 256>>>(Wk, p_Whi + (size_t)OK * DIMM, p_Wlo + (size_t)OK * DIMM, DIMM, C3);
    transpose_split<<<dim3(C3 / 32, DIMM / 32), 256>>>(Wv, p_Whi + (size_t)OV * DIMM, p_Wlo + (size_t)OV * DIMM, DIMM, C3);
    transpose_split<<<dim3(DIMM / 32, C3 / 32), 256>>>(Wt, p_Wthi, p_Wtlo, C3, DIMM);
    concat_bias<<<(C3X + 255) / 256, 256>>>(bq, bk, bv, p_bqkv);
    {
        int n4 = BB * SS * DIMM / 4;
        split_f32<<<(n4 + 255) / 256, 256>>>(x, p_xhi, p_xlo, n4);
    }

    const int M1 = BB * SS;   // 12552
    {   // fused QKV: one launch, N = 6912
        dim3 grid(C3X / 128, M1PAD / 128);
        gemm_bs<<<grid, 256, GEMM_SMEM>>>(p_xhi, p_xlo, p_Whi, p_Wlo, p_bqkv, p_qkv, M1, C3X, DIMM);
    }
    inter_cls_kernel<<<dim3(HH, BB), 256>>>();
    temporal_kernel<<<dim3(PP, HH, BB), 192>>>();

    const int M2 = BB * PP;   // 1560
    {
        int n4 = M2 * C3 / 4;
        split_f32<<<(n4 + 255) / 256, 256>>>(p_t1, p_t1hi, p_t1lo, n4);
        dim3 grid(DIMM / 128, M2PAD / 128);
        gemm_bs<<<grid, 256, GEMM_SMEM>>>(p_t1hi, p_t1lo, p_Wthi, p_Wtlo, bt, p_ti, M2, DIMM, C3);
    }
    {
        int n4 = M2 * DIMM / 4;
        split_f32<<<(n4 + 255) / 256, 256>>>(p_ti, p_tihi, p_tilo, n4);
        dim3 grid(C3X / 128, M2PAD / 128);
        gemm_bs<<<grid, 256, GEMM_SMEM>>>(p_tihi, p_tilo, p_Whi, p_Wlo, p_bqkv, p_q2kv, M2, C3X, DIMM);
    }
    {
        size_t smA = (size_t)(196 * 193 + 8 * D3 + 196) * 4;
        out_attn_kernel<<<dim3(1, HH, BB), 256, smA>>>(0, 196);
        size_t smB = (size_t)(8 * 193 + 8 * D3 + 8) * 4;
        out_attn_kernel<<<dim3(7, HH, BB), 256, smB>>>(1, 8);
    }
    final_rows_kernel<<<dim3(4, BB), 192, (size_t)9 * C3 * 4>>>(Wf, bf);
    {
        const size_t total4 = (size_t)BB * SS * DIMM / 4;
        bcast_kernel<<<(unsigned)((total4 + 255) / 256), 256>>>(out);
    }
}

// round 9
// speedup vs baseline: 2.0316x; 1.2424x over previous
#include <cuda_runtime.h>
#include <cuda_fp16.h>
#include <mma.h>
#include <cstdint>
#include <math.h>

using namespace nvcuda;

#define HH 12
#define NP 196
#define FF 8
#define DIMM 768
#define D3 192
#define BB 8
#define SS 1569
#define PP 195
#define C3 2304
#define C3X 6912            // fused QKV row width
#define OQ 0
#define OK 2304
#define OV 4608
#define SCALE_INV (1.0f/96.0f)

#define M1PAD 12672   // ceil(8*1569/128)*128
#define M2PAD 1664    // ceil(8*195/128)*128

// ---------------- scratch (device globals; zero-initialized) ----------------
__device__ float g_qkv[BB*SS*C3X];     // fused [x@Wq | x@Wk | x@Wv]
__device__ float g_t1[BB*PP*C3];
__device__ float g_ti[BB*PP*DIMM];
__device__ float g_q2kv[BB*PP*C3X];    // fused [ti@Wq | ti@Wk | ti@Wv]
__device__ float g_cls[BB*C3];
__device__ float g_t2[BB*FF*C3];
__device__ float g_rows[BB*9*DIMM];
__device__ float g_bqkv[C3X];
// fp16 A-side buffers (single digit, padded rows)
__device__ __half g_xh[M1PAD*DIMM];
__device__ __half g_t1h[M2PAD*C3];
__device__ __half g_tih[M2PAD*DIMM];
// fp16 two-digit transposed weights [N,K]
__device__ __half g_Wh[C3X*DIMM], g_Wl[C3X*DIMM];
__device__ __half g_Wth[DIMM*C3], g_Wtl[DIMM*C3];

// ---------------- helpers ------------------------------------------------------
__device__ __forceinline__ uint32_t smem_u32(const void* p) {
    uint32_t a;
    asm("{ .reg .u64 t; cvta.to.shared.u64 t, %1; cvt.u32.u64 %0, t; }" : "=r"(a) : "l"(p));
    return a;
}
#define CP_ASYNC16(dst_u32, src_ptr) \
    asm volatile("cp.async.cg.shared.global [%0], [%1], 16;" :: "r"(dst_u32), "l"(src_ptr))
#define CP_COMMIT() asm volatile("cp.async.commit_group;" ::: "memory")
#define CP_WAIT1()  asm volatile("cp.async.wait_group 1;" ::: "memory")

// ---------------- fp32 -> fp16 (A side) -----------------------------------------
__global__ void tohalf(const float* __restrict__ in, __half* __restrict__ out, int n4) {
    int i = blockIdx.x * blockDim.x + threadIdx.x;
    if (i >= n4) return;
    float4 v = ((const float4*)in)[i];
    ((__half2*)out)[i * 2 + 0] = __half2(__float2half(v.x), __float2half(v.y));
    ((__half2*)out)[i * 2 + 1] = __half2(__float2half(v.z), __float2half(v.w));
}

// ---------------- transpose + two-digit fp16 split: [K,N] -> [N,K] --------------
__global__ void transpose_split(const float* __restrict__ in,
                                __half* __restrict__ hi, __half* __restrict__ lo,
                                int K, int N) {
    __shared__ float t[32][33];
    const int n0 = blockIdx.x * 32, k0 = blockIdx.y * 32;
    const int tx = threadIdx.x & 31, ty = threadIdx.x >> 5;
#pragma unroll
    for (int i = 0; i < 32; i += 8)
        t[ty + i][tx] = in[(size_t)(k0 + ty + i) * N + n0 + tx];
    __syncthreads();
#pragma unroll
    for (int i = 0; i < 32; i += 8) {
        float v = t[tx][ty + i];
        __half h = __float2half(v);
        hi[(size_t)(n0 + ty + i) * K + k0 + tx] = h;
        lo[(size_t)(n0 + ty + i) * K + k0 + tx] = __float2half(v - __half2float(h));
    }
}

// ---------------- bias concat -----------------------------------------------------
__global__ void concat_bias(const float* __restrict__ bq, const float* __restrict__ bk,
                            const float* __restrict__ bv, float* __restrict__ outb) {
    int i = blockIdx.x * blockDim.x + threadIdx.x;
    if (i >= C3X) return;
    outb[i] = (i < OK) ? bq[i] : (i < OV) ? bk[i - OK] : bv[i - OV];
}

// ================= fp16 2-pass HMMA GEMM, 2-stage cp.async, 2 CTA/SM ============
// C(MxN) = A_fp16(MxK) @ [Bhi+Blo]([N,K])^T + bias, fp32 accumulate.
#define LDT 40
#define HT (128 * LDT * 2)          // 10240 bytes per fp16 tile
#define HSTAGE (3 * HT)             // Ah | Bh | Bl = 30720 per stage
#define H_SMEM 65536                // max(2*HSTAGE, 128*128*4 epilogue)

__global__ void __launch_bounds__(256, 2)
gemm_hs(const __half* __restrict__ A,
        const __half* __restrict__ Bh_g, const __half* __restrict__ Bl_g,
        const float* __restrict__ bias, float* __restrict__ C,
        int M, int N, int K) {
    extern __shared__ char smem[];
    const uint32_t smem_b = smem_u32(smem);
    const int tid = threadIdx.x;
    const int wid = tid >> 5;
    const int wm = wid & 3, wn = wid >> 2;
    const int rowA0 = blockIdx.y * 128;
    const int n0 = blockIdx.x * 128;
    const int nch = K >> 5;

    const int r_cp = tid >> 1;
    const int s_cp = (tid & 1) * 2;
    const __half* srcs[3];
    srcs[0] = A    + (size_t)(rowA0 + r_cp) * K;
    srcs[1] = Bh_g + (size_t)(n0 + r_cp) * K;
    srcs[2] = Bl_g + (size_t)(n0 + r_cp) * K;
    const uint32_t dst_row = smem_b + r_cp * (LDT * 2);

    auto issue_stage = [&](int c, int buf) {
        const int k0 = c << 5;
        const uint32_t sb = buf * HSTAGE;
#pragma unroll
        for (int t = 0; t < 3; t++) {
            const __half* src = srcs[t] + k0 + s_cp * 8;
            const uint32_t dst = dst_row + sb + t * HT + s_cp * 16;
            CP_ASYNC16(dst, src);
            CP_ASYNC16(dst + 16, src + 8);
        }
    };

    wmma::fragment<wmma::accumulator, 16, 16, 16, float> acc[2][4];
#pragma unroll
    for (int i = 0; i < 2; i++)
#pragma unroll
        for (int j = 0; j < 4; j++) wmma::fill_fragment(acc[i][j], 0.f);

    issue_stage(0, 0);
    CP_COMMIT();

    for (int c = 0; c < nch; c++) {
        if (c + 1 < nch) issue_stage(c + 1, (c + 1) & 1);
        CP_COMMIT();
        CP_WAIT1();
        __syncthreads();

        const __half* Ah = (const __half*)(smem + (c & 1) * HSTAGE);
        const __half* Bh = Ah + 128 * LDT;
        const __half* Bl = Bh + 128 * LDT;
#pragma unroll
        for (int kk = 0; kk < 32; kk += 16) {
            wmma::fragment<wmma::matrix_a, 16, 16, 16, __half, wmma::row_major> ah[2];
#pragma unroll
            for (int i = 0; i < 2; i++)
                wmma::load_matrix_sync(ah[i], Ah + (wm * 32 + i * 16) * LDT + kk, LDT);
#pragma unroll
            for (int j = 0; j < 4; j++) {
                {
                    wmma::fragment<wmma::matrix_b, 16, 16, 16, __half, wmma::col_major> bh;
                    wmma::load_matrix_sync(bh, Bh + (wn * 64 + j * 16) * LDT + kk, LDT);
                    wmma::mma_sync(acc[0][j], ah[0], bh, acc[0][j]);
                    wmma::mma_sync(acc[1][j], ah[1], bh, acc[1][j]);
                }
                {
                    wmma::fragment<wmma::matrix_b, 16, 16, 16, __half, wmma::col_major> bl;
                    wmma::load_matrix_sync(bl, Bl + (wn * 64 + j * 16) * LDT + kk, LDT);
                    wmma::mma_sync(acc[0][j], ah[0], bl, acc[0][j]);
                    wmma::mma_sync(acc[1][j], ah[1], bl, acc[1][j]);
                }
            }
        }
        __syncthreads();
    }

    float* sC = (float*)smem;
#pragma unroll
    for (int i = 0; i < 2; i++)
#pragma unroll
        for (int j = 0; j < 4; j++)
            wmma::store_matrix_sync(sC + (wm * 32 + i * 16) * 128 + wn * 64 + j * 16,
                                    acc[i][j], 128, wmma::mem_row_major);
    __syncthreads();
#pragma unroll
    for (int i = 0; i < 16; i++) {
        const int f = i * 256 + tid;
        const int r = f >> 5, c4 = f & 31;
        const int gm = rowA0 + r;
        if (gm < M) {
            float4 v = *(float4*)(sC + r * 128 + c4 * 4);
            const int n = n0 + c4 * 4;
            v.x += bias[n + 0];
            v.y += bias[n + 1];
            v.z += bias[n + 2];
            v.w += bias[n + 3];
            *(float4*)(C + (size_t)gm * N + n) = v;
        }
    }
}

// ---------------- inter_cls (fused-buffer strides) --------------------------------
__global__ void inter_cls_kernel() {
    __shared__ float sc[SS];
    __shared__ float red[256];
    __shared__ float part[8 * D3];
    const int h = blockIdx.x, b = blockIdx.y;
    const int tid = threadIdx.x, lane = tid & 31, wid = tid >> 5;
    const float* baseq = g_qkv + (size_t)b * SS * C3X + OQ + h * D3;
    const float* basek = g_qkv + (size_t)b * SS * C3X + OK + h * D3;
    const float* basev = g_qkv + (size_t)b * SS * C3X + OV + h * D3;

    float qv[6];
#pragma unroll
    for (int i = 0; i < 6; i++) qv[i] = baseq[lane + 32 * i];

    for (int t = wid; t < SS; t += 8) {
        const float* kr = basek + (size_t)t * C3X;
        float p = 0.f;
#pragma unroll
        for (int i = 0; i < 6; i++) p += qv[i] * kr[lane + 32 * i];
#pragma unroll
        for (int off = 16; off; off >>= 1) p += __shfl_xor_sync(0xffffffffu, p, off);
        if (lane == 0) sc[t] = p * SCALE_INV;
    }
    __syncthreads();

    float m = -1e30f;
    for (int t = tid; t < SS; t += 256) m = fmaxf(m, sc[t]);
    red[tid] = m; __syncthreads();
    for (int s = 128; s; s >>= 1) { if (tid < s) red[tid] = fmaxf(red[tid], red[tid + s]); __syncthreads(); }
    m = red[0]; __syncthreads();

    float z = 0.f;
    for (int t = tid; t < SS; t += 256) { float e = expf(sc[t] - m); sc[t] = e; z += e; }
    red[tid] = z; __syncthreads();
    for (int s = 128; s; s >>= 1) { if (tid < s) red[tid] += red[tid + s]; __syncthreads(); }
    const float invZ = 1.f / red[0];
    __syncthreads();

    float a[6] = {0.f, 0.f, 0.f, 0.f, 0.f, 0.f};
    for (int t = wid; t < SS; t += 8) {
        const float p = sc[t];
        const float* vr = basev + (size_t)t * C3X;
#pragma unroll
        for (int i = 0; i < 6; i++) a[i] += p * vr[lane + 32 * i];
    }
#pragma unroll
    for (int i = 0; i < 6; i++) part[wid * D3 + lane + 32 * i] = a[i];
    __syncthreads();
    if (tid < D3) {
        float s = 0.f;
#pragma unroll
        for (int w = 0; w < 8; w++) s += part[w * D3 + tid];
        g_cls[b * C3 + h * D3 + tid] = s * invZ;
    }
}

// ---------------- temporal attention ----------------------------------------------
__global__ void temporal_kernel() {
    __shared__ float qs[8 * 193];
    __shared__ float ks[8 * 193];
    __shared__ float sc[8 * 9];
    __shared__ float cw[8];
    const int p = blockIdx.x, h = blockIdx.y, b = blockIdx.z;
    const int tid = threadIdx.x;
    const size_t bb = (size_t)b * SS * C3X;

    for (int e = tid; e < 8 * D3; e += 192) {
        int f = e / D3, j = e - f * D3;
        int tok = f * NP + p + 2;
        qs[f * 193 + j] = g_qkv[bb + (size_t)tok * C3X + OQ + h * D3 + j];
        ks[f * 193 + j] = g_qkv[bb + (size_t)tok * C3X + OV + h * D3 + j];
    }
    __syncthreads();

    if (tid < 64) {
        int f = tid >> 3, g = tid & 7;
        float s = 0.f;
        for (int j = 0; j < D3; j++) s += qs[f * 193 + j] * ks[g * 193 + j];
        sc[f * 9 + g] = s * SCALE_INV;
    }
    __syncthreads();

    if (tid < 8) {
        int f = tid;
        float mx = -1e30f;
        for (int g = 0; g < 8; g++) mx = fmaxf(mx, sc[f * 9 + g]);
        float z = 0.f;
        for (int g = 0; g < 8; g++) { float e = expf(sc[f * 9 + g] - mx); sc[f * 9 + g] = e; z += e; }
        float inv = 1.f / z;
        for (int g = 0; g < 8; g++) sc[f * 9 + g] *= inv;
    }
    __syncthreads();
    if (tid < 8) {
        int g = tid;
        float s = 0.f;
        for (int f = 0; f < 8; f++) s += sc[f * 9 + g];
        cw[g] = s;
    }
    __syncthreads();

    {
        int d = tid;
        float acc = 0.f;
#pragma unroll
        for (int g = 0; g < 8; g++) {
            int tok = g * NP + p + 2;
            acc += cw[g] * g_qkv[bb + (size_t)tok * C3X + OK + h * D3 + d];
        }
        g_t1[((size_t)b * PP + p) * C3 + h * D3 + d] = acc;
    }
}

// ---------------- output-stage attention -------------------------------------------
__global__ void out_attn_kernel(int xi_base, int nk) {
    extern __shared__ float sm[];
    float* Kb = sm;
    float* qb = sm + nk * 193;
    float* w  = qb + 8 * D3;
    const int xi = xi_base + blockIdx.x;
    const int h = blockIdx.y, b = blockIdx.z;
    const int tid = threadIdx.x, lane = tid & 31, wid = tid >> 5;
    const size_t rbase = (size_t)b * PP * C3X + h * D3;

    for (int e = tid; e < nk * D3; e += 256) {
        int r = e / D3, j = e - r * D3;
        int kp = (nk == 196) ? (r % PP) : (xi + r);
        Kb[r * 193 + j] = g_q2kv[rbase + (size_t)kp * C3X + OV + j];
    }
    for (int k = tid; k < nk; k += 256) w[k] = 0.f;
    __syncthreads();

    for (int q = wid; q < 196; q += 8) {
        int qp = (xi + q) % PP;
        for (int j = lane; j < D3; j += 32)
            qb[wid * D3 + j] = g_q2kv[rbase + (size_t)qp * C3X + OQ + j];
        __syncwarp();

        float s[7];
        int cnt = 0;
        for (int k = lane; k < nk; k += 32) {
            float d = 0.f;
            const float* kr = Kb + k * 193;
            const float* qr = qb + wid * D3;
            for (int j = 0; j < D3; j++) d += qr[j] * kr[j];
            s[cnt++] = d * SCALE_INV;
        }
        float mx = -1e30f;
        for (int c = 0; c < cnt; c++) mx = fmaxf(mx, s[c]);
#pragma unroll
        for (int off = 16; off; off >>= 1) mx = fmaxf(mx, __shfl_xor_sync(0xffffffffu, mx, off));
        float z = 0.f;
        for (int c = 0; c < cnt; c++) { float e = expf(s[c] - mx); s[c] = e; z += e; }
#pragma unroll
        for (int off = 16; off; off >>= 1) z += __shfl_xor_sync(0xffffffffu, z, off);
        float inv = 1.f / z;
        int c = 0;
        for (int k = lane; k < nk; k += 32, c++) atomicAdd(&w[k], s[c] * inv);
        __syncwarp();
    }
    __syncthreads();

    if (tid < D3) {
        float acc = 0.f;
        for (int k = 0; k < nk; k++) {
            int kp = (nk == 196) ? (k % PP) : (xi + k);
            acc += w[k] * g_q2kv[rbase + (size_t)kp * C3X + OK + tid];
        }
        g_t2[((size_t)b * FF + xi) * C3 + h * D3 + tid] = acc;
    }
}

// ---------------- final 9 rows per batch ---------------------------------------------
__global__ void final_rows_kernel(const float* __restrict__ Wf, const float* __restrict__ bf) {
    extern __shared__ float As[];
    const int cb = blockIdx.x, b = blockIdx.y;
    const int tid = threadIdx.x;
    for (int e = tid; e < 9 * C3; e += 192) {
        int r = e / C3, k = e - r * C3;
        As[e] = (r == 0) ? g_cls[b * C3 + k] : g_t2[((size_t)b * FF + (r - 1)) * C3 + k];
    }
    __syncthreads();
    const int c = cb * 192 + tid;
    float acc[9];
#pragma unroll
    for (int r = 0; r < 9; r++) acc[r] = 0.f;
    for (int k = 0; k < C3; k++) {
        float wv = Wf[(size_t)k * DIMM + c];
#pragma unroll
        for (int r = 0; r < 9; r++) acc[r] += As[r * C3 + k] * wv;
    }
    float bv = bf[c];
#pragma unroll
    for (int r = 0; r < 9; r++)
        g_rows[((size_t)b * 9 + r) * DIMM + c] = acc[r] + bv;
}

// ---------------- broadcast -> output --------------------------------------------------
__global__ void bcast_kernel(float* __restrict__ out) {
    size_t i4 = (size_t)blockIdx.x * blockDim.x + threadIdx.x;
    const size_t total4 = (size_t)BB * SS * DIMM / 4;
    if (i4 >= total4) return;
    size_t idx = i4 * 4;
    int c = idx % DIMM;
    size_t rs = idx / DIMM;
    int s = rs % SS;
    int b = rs / SS;
    int r = (s == 0) ? 0 : 1 + ((s - 1) & 7);
    ((float4*)out)[i4] = *(const float4*)(g_rows + ((size_t)b * 9 + r) * DIMM + c);
}

// ---------------- launch ---------------------------------------------------------------
extern "C" void kernel_launch(void* const* d_in, const int* in_sizes, int n_in,
                              void* d_out, int out_size) {
    const float* x  = (const float*)d_in[0];
    const float* Wq = (const float*)d_in[1];
    const float* bq = (const float*)d_in[2];
    const float* Wk = (const float*)d_in[3];
    const float* bk = (const float*)d_in[4];
    const float* Wv = (const float*)d_in[5];
    const float* bv = (const float*)d_in[6];
    const float* Wt = (const float*)d_in[7];
    const float* bt = (const float*)d_in[8];
    const float* Wf = (const float*)d_in[9];
    const float* bf = (const float*)d_in[10];
    float* out = (float*)d_out;

    float *p_qkv, *p_t1, *p_ti, *p_q2kv, *p_bqkv;
    cudaGetSymbolAddress((void**)&p_qkv, g_qkv);
    cudaGetSymbolAddress((void**)&p_t1, g_t1);
    cudaGetSymbolAddress((void**)&p_ti, g_ti);
    cudaGetSymbolAddress((void**)&p_q2kv, g_q2kv);
    cudaGetSymbolAddress((void**)&p_bqkv, g_bqkv);
    __half *p_xh, *p_t1h, *p_tih, *p_Wh, *p_Wl, *p_Wth, *p_Wtl;
    cudaGetSymbolAddress((void**)&p_xh, g_xh);
    cudaGetSymbolAddress((void**)&p_t1h, g_t1h);
    cudaGetSymbolAddress((void**)&p_tih, g_tih);
    cudaGetSymbolAddress((void**)&p_Wh, g_Wh);
    cudaGetSymbolAddress((void**)&p_Wl, g_Wl);
    cudaGetSymbolAddress((void**)&p_Wth, g_Wth);
    cudaGetSymbolAddress((void**)&p_Wtl, g_Wtl);

    cudaFuncSetAttribute(gemm_hs, cudaFuncAttributeMaxDynamicSharedMemorySize, H_SMEM);
    cudaFuncSetAttribute(out_attn_kernel, cudaFuncAttributeMaxDynamicSharedMemorySize, 160000);
    cudaFuncSetAttribute(final_rows_kernel, cudaFuncAttributeMaxDynamicSharedMemorySize, 9 * C3 * 4);

    // fused weight transpose+split -> [6912, 768] fp16 hi/lo
    transpose_split<<<dim3(C3 / 32, DIMM / 32), 256>>>(Wq, p_Wh + (size_t)OQ * DIMM, p_Wl + (size_t)OQ * DIMM, DIMM, C3);
    transpose_split<<<dim3(C3 / 32, DIMM / 32), 256>>>(Wk, p_Wh + (size_t)OK * DIMM, p_Wl + (size_t)OK * DIMM, DIMM, C3);
    transpose_split<<<dim3(C3 / 32, DIMM / 32), 256>>>(Wv, p_Wh + (size_t)OV * DIMM, p_Wl + (size_t)OV * DIMM, DIMM, C3);
    transpose_split<<<dim3(DIMM / 32, C3 / 32), 256>>>(Wt, p_Wth, p_Wtl, C3, DIMM);
    concat_bias<<<(C3X + 255) / 256, 256>>>(bq, bk, bv, p_bqkv);
    {
        int n4 = BB * SS * DIMM / 4;
        tohalf<<<(n4 + 255) / 256, 256>>>(x, p_xh, n4);
    }

    const int M1 = BB * SS;   // 12552
    {   // fused QKV: one launch, N = 6912
        dim3 grid(C3X / 128, M1PAD / 128);
        gemm_hs<<<grid, 256, H_SMEM>>>(p_xh, p_Wh, p_Wl, p_bqkv, p_qkv, M1, C3X, DIMM);
    }
    inter_cls_kernel<<<dim3(HH, BB), 256>>>();
    temporal_kernel<<<dim3(PP, HH, BB), 192>>>();

    const int M2 = BB * PP;   // 1560
    {
        int n4 = M2 * C3 / 4;
        tohalf<<<(n4 + 255) / 256, 256>>>(p_t1, p_t1h, n4);
        dim3 grid(DIMM / 128, M2PAD / 128);
        gemm_hs<<<grid, 256, H_SMEM>>>(p_t1h, p_Wth, p_Wtl, bt, p_ti, M2, DIMM, C3);
    }
    {
        int n4 = M2 * DIMM / 4;
        tohalf<<<(n4 + 255) / 256, 256>>>(p_ti, p_tih, n4);
        dim3 grid(C3X / 128, M2PAD / 128);
        gemm_hs<<<grid, 256, H_SMEM>>>(p_tih, p_Wh, p_Wl, p_bqkv, p_q2kv, M2, C3X, DIMM);
    }
    {
        size_t smA = (size_t)(196 * 193 + 8 * D3 + 196) * 4;
        out_attn_kernel<<<dim3(1, HH, BB), 256, smA>>>(0, 196);
        size_t smB = (size_t)(8 * 193 + 8 * D3 + 8) * 4;
        out_attn_kernel<<<dim3(7, HH, BB), 256, smB>>>(1, 8);
    }
    final_rows_kernel<<<dim3(4, BB), 192, (size_t)9 * C3 * 4>>>(Wf, bf);
    {
        const size_t total4 = (size_t)BB * SS * DIMM / 4;
        bcast_kernel<<<(unsigned)((total4 + 255) / 256), 256>>>(out);
    }
}

// round 10
// speedup vs baseline: 2.4993x; 1.2302x over previous
#include <cuda_runtime.h>
#include <cuda_fp16.h>
#include <mma.h>
#include <cstdint>
#include <math.h>

using namespace nvcuda;

#define HH 12
#define NP 196
#define FF 8
#define DIMM 768
#define D3 192
#define BB 8
#define SS 1569
#define PP 195
#define C3 2304
#define C3X 6912            // fused QKV row width
#define OQ 0
#define OK 2304
#define OV 4608
#define SCALE_INV (1.0f/96.0f)

#define M1PAD 12672   // ceil(8*1569/128)*128
#define M2PAD 1664    // ceil(8*195/128)*128

// ---------------- scratch (device globals; zero-initialized) ----------------
__device__ float g_qkv[BB*SS*C3X];     // fused [x@Wq | x@Wk | x@Wv]
__device__ float g_t1[BB*PP*C3];
__device__ float g_ti[BB*PP*DIMM];
__device__ float g_q2kv[BB*PP*C3X];    // fused [ti@Wq | ti@Wk | ti@Wv]
__device__ float g_cls[BB*C3];
__device__ float g_t2[BB*FF*C3];
__device__ float g_rows[BB*9*DIMM];
__device__ float g_bqkv[C3X];
// fp16 A-side buffers (padded rows)
__device__ __half g_xh[M1PAD*DIMM];
__device__ __half g_t1h[M2PAD*C3];
__device__ __half g_tih[M2PAD*DIMM];
// fp16 transposed weights [N,K]
__device__ __half g_Wh[C3X*DIMM];
__device__ __half g_Wth[DIMM*C3];

// ---------------- helpers ------------------------------------------------------
__device__ __forceinline__ uint32_t smem_u32(const void* p) {
    uint32_t a;
    asm("{ .reg .u64 t; cvta.to.shared.u64 t, %1; cvt.u32.u64 %0, t; }" : "=r"(a) : "l"(p));
    return a;
}
#define CP_ASYNC16(dst_u32, src_ptr) \
    asm volatile("cp.async.cg.shared.global [%0], [%1], 16;" :: "r"(dst_u32), "l"(src_ptr))
#define CP_COMMIT() asm volatile("cp.async.commit_group;" ::: "memory")
#define CP_WAIT1()  asm volatile("cp.async.wait_group 1;" ::: "memory")

// ---------------- fp32 -> fp16 -----------------------------------------------------
__global__ void tohalf(const float* __restrict__ in, __half* __restrict__ out, int n4) {
    int i = blockIdx.x * blockDim.x + threadIdx.x;
    if (i >= n4) return;
    float4 v = ((const float4*)in)[i];
    ((__half2*)out)[i * 2 + 0] = __half2(__float2half(v.x), __float2half(v.y));
    ((__half2*)out)[i * 2 + 1] = __half2(__float2half(v.z), __float2half(v.w));
}

// ---------------- transpose to fp16: [K,N] -> [N,K] --------------------------------
__global__ void transpose_h(const float* __restrict__ in, __half* __restrict__ outh,
                            int K, int N) {
    __shared__ float t[32][33];
    const int n0 = blockIdx.x * 32, k0 = blockIdx.y * 32;
    const int tx = threadIdx.x & 31, ty = threadIdx.x >> 5;
#pragma unroll
    for (int i = 0; i < 32; i += 8)
        t[ty + i][tx] = in[(size_t)(k0 + ty + i) * N + n0 + tx];
    __syncthreads();
#pragma unroll
    for (int i = 0; i < 32; i += 8)
        outh[(size_t)(n0 + ty + i) * K + k0 + tx] = __float2half(t[tx][ty + i]);
}

// ---------------- bias concat --------------------------------------------------------
__global__ void concat_bias(const float* __restrict__ bq, const float* __restrict__ bk,
                            const float* __restrict__ bv, float* __restrict__ outb) {
    int i = blockIdx.x * blockDim.x + threadIdx.x;
    if (i >= C3X) return;
    outb[i] = (i < OK) ? bq[i] : (i < OV) ? bk[i - OK] : bv[i - OV];
}

// ================= fp16 1-pass HMMA GEMM, 2-stage cp.async, 2 CTA/SM ===============
// C(MxN) = A_fp16(MxK) @ B_fp16([N,K])^T + bias, fp32 accumulate.
#define LDT 40
#define HT (128 * LDT * 2)          // 10240 bytes per fp16 tile
#define HSTAGE (2 * HT)             // A | B = 20480 per stage
#define H_SMEM 65536                // epilogue staging needs 128*128*4

__global__ void __launch_bounds__(256, 2)
gemm_h1(const __half* __restrict__ A, const __half* __restrict__ B_g,
        const float* __restrict__ bias, float* __restrict__ C,
        int M, int N, int K) {
    extern __shared__ char smem[];
    const uint32_t smem_b = smem_u32(smem);
    const int tid = threadIdx.x;
    const int wid = tid >> 5;
    const int wm = wid & 3, wn = wid >> 2;
    const int rowA0 = blockIdx.y * 128;
    const int n0 = blockIdx.x * 128;
    const int nch = K >> 5;

    const int r_cp = tid >> 1;
    const int s_cp = (tid & 1) * 2;
    const __half* srcA = A   + (size_t)(rowA0 + r_cp) * K + s_cp * 8;
    const __half* srcB = B_g + (size_t)(n0 + r_cp) * K + s_cp * 8;
    const uint32_t dst_row = smem_b + r_cp * (LDT * 2) + s_cp * 16;

    auto issue_stage = [&](int c, int buf) {
        const int k0 = c << 5;
        const uint32_t sb = buf * HSTAGE;
        CP_ASYNC16(dst_row + sb, srcA + k0);
        CP_ASYNC16(dst_row + sb + 16, srcA + k0 + 8);
        CP_ASYNC16(dst_row + sb + HT, srcB + k0);
        CP_ASYNC16(dst_row + sb + HT + 16, srcB + k0 + 8);
    };

    wmma::fragment<wmma::accumulator, 16, 16, 16, float> acc[2][4];
#pragma unroll
    for (int i = 0; i < 2; i++)
#pragma unroll
        for (int j = 0; j < 4; j++) wmma::fill_fragment(acc[i][j], 0.f);

    issue_stage(0, 0);
    CP_COMMIT();

    for (int c = 0; c < nch; c++) {
        if (c + 1 < nch) issue_stage(c + 1, (c + 1) & 1);
        CP_COMMIT();
        CP_WAIT1();
        __syncthreads();

        const __half* Ah = (const __half*)(smem + (c & 1) * HSTAGE);
        const __half* Bh = Ah + 128 * LDT;
#pragma unroll
        for (int kk = 0; kk < 32; kk += 16) {
            wmma::fragment<wmma::matrix_a, 16, 16, 16, __half, wmma::row_major> ah[2];
#pragma unroll
            for (int i = 0; i < 2; i++)
                wmma::load_matrix_sync(ah[i], Ah + (wm * 32 + i * 16) * LDT + kk, LDT);
#pragma unroll
            for (int j = 0; j < 4; j++) {
                wmma::fragment<wmma::matrix_b, 16, 16, 16, __half, wmma::col_major> bh;
                wmma::load_matrix_sync(bh, Bh + (wn * 64 + j * 16) * LDT + kk, LDT);
                wmma::mma_sync(acc[0][j], ah[0], bh, acc[0][j]);
                wmma::mma_sync(acc[1][j], ah[1], bh, acc[1][j]);
            }
        }
        __syncthreads();
    }

    float* sC = (float*)smem;
#pragma unroll
    for (int i = 0; i < 2; i++)
#pragma unroll
        for (int j = 0; j < 4; j++)
            wmma::store_matrix_sync(sC + (wm * 32 + i * 16) * 128 + wn * 64 + j * 16,
                                    acc[i][j], 128, wmma::mem_row_major);
    __syncthreads();
#pragma unroll
    for (int i = 0; i < 16; i++) {
        const int f = i * 256 + tid;
        const int r = f >> 5, c4 = f & 31;
        const int gm = rowA0 + r;
        if (gm < M) {
            float4 v = *(float4*)(sC + r * 128 + c4 * 4);
            const int n = n0 + c4 * 4;
            v.x += bias[n + 0];
            v.y += bias[n + 1];
            v.z += bias[n + 2];
            v.w += bias[n + 3];
            *(float4*)(C + (size_t)gm * N + n) = v;
        }
    }
}

// ---------------- inter_cls (fused-buffer strides) -----------------------------------
__global__ void inter_cls_kernel() {
    __shared__ float sc[SS];
    __shared__ float red[256];
    __shared__ float part[8 * D3];
    const int h = blockIdx.x, b = blockIdx.y;
    const int tid = threadIdx.x, lane = tid & 31, wid = tid >> 5;
    const float* baseq = g_qkv + (size_t)b * SS * C3X + OQ + h * D3;
    const float* basek = g_qkv + (size_t)b * SS * C3X + OK + h * D3;
    const float* basev = g_qkv + (size_t)b * SS * C3X + OV + h * D3;

    float qv[6];
#pragma unroll
    for (int i = 0; i < 6; i++) qv[i] = baseq[lane + 32 * i];

    for (int t = wid; t < SS; t += 8) {
        const float* kr = basek + (size_t)t * C3X;
        float p = 0.f;
#pragma unroll
        for (int i = 0; i < 6; i++) p += qv[i] * kr[lane + 32 * i];
#pragma unroll
        for (int off = 16; off; off >>= 1) p += __shfl_xor_sync(0xffffffffu, p, off);
        if (lane == 0) sc[t] = p * SCALE_INV;
    }
    __syncthreads();

    float m = -1e30f;
    for (int t = tid; t < SS; t += 256) m = fmaxf(m, sc[t]);
    red[tid] = m; __syncthreads();
    for (int s = 128; s; s >>= 1) { if (tid < s) red[tid] = fmaxf(red[tid], red[tid + s]); __syncthreads(); }
    m = red[0]; __syncthreads();

    float z = 0.f;
    for (int t = tid; t < SS; t += 256) { float e = expf(sc[t] - m); sc[t] = e; z += e; }
    red[tid] = z; __syncthreads();
    for (int s = 128; s; s >>= 1) { if (tid < s) red[tid] += red[tid + s]; __syncthreads(); }
    const float invZ = 1.f / red[0];
    __syncthreads();

    float a[6] = {0.f, 0.f, 0.f, 0.f, 0.f, 0.f};
    for (int t = wid; t < SS; t += 8) {
        const float p = sc[t];
        const float* vr = basev + (size_t)t * C3X;
#pragma unroll
        for (int i = 0; i < 6; i++) a[i] += p * vr[lane + 32 * i];
    }
#pragma unroll
    for (int i = 0; i < 6; i++) part[wid * D3 + lane + 32 * i] = a[i];
    __syncthreads();
    if (tid < D3) {
        float s = 0.f;
#pragma unroll
        for (int w = 0; w < 8; w++) s += part[w * D3 + tid];
        g_cls[b * C3 + h * D3 + tid] = s * invZ;
    }
}

// ---------------- temporal attention --------------------------------------------------
__global__ void temporal_kernel() {
    __shared__ float qs[8 * 193];
    __shared__ float ks[8 * 193];
    __shared__ float sc[8 * 9];
    __shared__ float cw[8];
    const int p = blockIdx.x, h = blockIdx.y, b = blockIdx.z;
    const int tid = threadIdx.x;
    const size_t bb = (size_t)b * SS * C3X;

    for (int e = tid; e < 8 * D3; e += 192) {
        int f = e / D3, j = e - f * D3;
        int tok = f * NP + p + 2;
        qs[f * 193 + j] = g_qkv[bb + (size_t)tok * C3X + OQ + h * D3 + j];
        ks[f * 193 + j] = g_qkv[bb + (size_t)tok * C3X + OV + h * D3 + j];
    }
    __syncthreads();

    if (tid < 64) {
        int f = tid >> 3, g = tid & 7;
        float s = 0.f;
        for (int j = 0; j < D3; j++) s += qs[f * 193 + j] * ks[g * 193 + j];
        sc[f * 9 + g] = s * SCALE_INV;
    }
    __syncthreads();

    if (tid < 8) {
        int f = tid;
        float mx = -1e30f;
        for (int g = 0; g < 8; g++) mx = fmaxf(mx, sc[f * 9 + g]);
        float z = 0.f;
        for (int g = 0; g < 8; g++) { float e = expf(sc[f * 9 + g] - mx); sc[f * 9 + g] = e; z += e; }
        float inv = 1.f / z;
        for (int g = 0; g < 8; g++) sc[f * 9 + g] *= inv;
    }
    __syncthreads();
    if (tid < 8) {
        int g = tid;
        float s = 0.f;
        for (int f = 0; f < 8; f++) s += sc[f * 9 + g];
        cw[g] = s;
    }
    __syncthreads();

    {
        int d = tid;
        float acc = 0.f;
#pragma unroll
        for (int g = 0; g < 8; g++) {
            int tok = g * NP + p + 2;
            acc += cw[g] * g_qkv[bb + (size_t)tok * C3X + OK + h * D3 + d];
        }
        g_t1[((size_t)b * PP + p) * C3 + h * D3 + d] = acc;
    }
}

// ---------------- output-stage attention ----------------------------------------------
__global__ void out_attn_kernel(int xi_base, int nk) {
    extern __shared__ float sm[];
    float* Kb = sm;
    float* qb = sm + nk * 193;
    float* w  = qb + 8 * D3;
    const int xi = xi_base + blockIdx.x;
    const int h = blockIdx.y, b = blockIdx.z;
    const int tid = threadIdx.x, lane = tid & 31, wid = tid >> 5;
    const size_t rbase = (size_t)b * PP * C3X + h * D3;

    for (int e = tid; e < nk * D3; e += 256) {
        int r = e / D3, j = e - r * D3;
        int kp = (nk == 196) ? (r % PP) : (xi + r);
        Kb[r * 193 + j] = g_q2kv[rbase + (size_t)kp * C3X + OV + j];
    }
    for (int k = tid; k < nk; k += 256) w[k] = 0.f;
    __syncthreads();

    for (int q = wid; q < 196; q += 8) {
        int qp = (xi + q) % PP;
        for (int j = lane; j < D3; j += 32)
            qb[wid * D3 + j] = g_q2kv[rbase + (size_t)qp * C3X + OQ + j];
        __syncwarp();

        float s[7];
        int cnt = 0;
        for (int k = lane; k < nk; k += 32) {
            float d = 0.f;
            const float* kr = Kb + k * 193;
            const float* qr = qb + wid * D3;
            for (int j = 0; j < D3; j++) d += qr[j] * kr[j];
            s[cnt++] = d * SCALE_INV;
        }
        float mx = -1e30f;
        for (int c = 0; c < cnt; c++) mx = fmaxf(mx, s[c]);
#pragma unroll
        for (int off = 16; off; off >>= 1) mx = fmaxf(mx, __shfl_xor_sync(0xffffffffu, mx, off));
        float z = 0.f;
        for (int c = 0; c < cnt; c++) { float e = expf(s[c] - mx); s[c] = e; z += e; }
#pragma unroll
        for (int off = 16; off; off >>= 1) z += __shfl_xor_sync(0xffffffffu, z, off);
        float inv = 1.f / z;
        int c = 0;
        for (int k = lane; k < nk; k += 32, c++) atomicAdd(&w[k], s[c] * inv);
        __syncwarp();
    }
    __syncthreads();

    if (tid < D3) {
        float acc = 0.f;
        for (int k = 0; k < nk; k++) {
            int kp = (nk == 196) ? (k % PP) : (xi + k);
            acc += w[k] * g_q2kv[rbase + (size_t)kp * C3X + OK + tid];
        }
        g_t2[((size_t)b * FF + xi) * C3 + h * D3 + tid] = acc;
    }
}

// ---------------- final 9 rows per batch ------------------------------------------------
__global__ void final_rows_kernel(const float* __restrict__ Wf, const float* __restrict__ bf) {
    extern __shared__ float As[];
    const int cb = blockIdx.x, b = blockIdx.y;
    const int tid = threadIdx.x;
    for (int e = tid; e < 9 * C3; e += 192) {
        int r = e / C3, k = e - r * C3;
        As[e] = (r == 0) ? g_cls[b * C3 + k] : g_t2[((size_t)b * FF + (r - 1)) * C3 + k];
    }
    __syncthreads();
    const int c = cb * 192 + tid;
    float acc[9];
#pragma unroll
    for (int r = 0; r < 9; r++) acc[r] = 0.f;
    for (int k = 0; k < C3; k++) {
        float wv = Wf[(size_t)k * DIMM + c];
#pragma unroll
        for (int r = 0; r < 9; r++) acc[r] += As[r * C3 + k] * wv;
    }
    float bv = bf[c];
#pragma unroll
    for (int r = 0; r < 9; r++)
        g_rows[((size_t)b * 9 + r) * DIMM + c] = acc[r] + bv;
}

// ---------------- broadcast -> output -----------------------------------------------------
__global__ void bcast_kernel(float* __restrict__ out) {
    size_t i4 = (size_t)blockIdx.x * blockDim.x + threadIdx.x;
    const size_t total4 = (size_t)BB * SS * DIMM / 4;
    if (i4 >= total4) return;
    size_t idx = i4 * 4;
    int c = idx % DIMM;
    size_t rs = idx / DIMM;
    int s = rs % SS;
    int b = rs / SS;
    int r = (s == 0) ? 0 : 1 + ((s - 1) & 7);
    ((float4*)out)[i4] = *(const float4*)(g_rows + ((size_t)b * 9 + r) * DIMM + c);
}

// ---------------- launch ------------------------------------------------------------------
extern "C" void kernel_launch(void* const* d_in, const int* in_sizes, int n_in,
                              void* d_out, int out_size) {
    const float* x  = (const float*)d_in[0];
    const float* Wq = (const float*)d_in[1];
    const float* bq = (const float*)d_in[2];
    const float* Wk = (const float*)d_in[3];
    const float* bk = (const float*)d_in[4];
    const float* Wv = (const float*)d_in[5];
    const float* bv = (const float*)d_in[6];
    const float* Wt = (const float*)d_in[7];
    const float* bt = (const float*)d_in[8];
    const float* Wf = (const float*)d_in[9];
    const float* bf = (const float*)d_in[10];
    float* out = (float*)d_out;

    float *p_qkv, *p_t1, *p_ti, *p_q2kv, *p_bqkv;
    cudaGetSymbolAddress((void**)&p_qkv, g_qkv);
    cudaGetSymbolAddress((void**)&p_t1, g_t1);
    cudaGetSymbolAddress((void**)&p_ti, g_ti);
    cudaGetSymbolAddress((void**)&p_q2kv, g_q2kv);
    cudaGetSymbolAddress((void**)&p_bqkv, g_bqkv);
    __half *p_xh, *p_t1h, *p_tih, *p_Wh, *p_Wth;
    cudaGetSymbolAddress((void**)&p_xh, g_xh);
    cudaGetSymbolAddress((void**)&p_t1h, g_t1h);
    cudaGetSymbolAddress((void**)&p_tih, g_tih);
    cudaGetSymbolAddress((void**)&p_Wh, g_Wh);
    cudaGetSymbolAddress((void**)&p_Wth, g_Wth);

    cudaFuncSetAttribute(gemm_h1, cudaFuncAttributeMaxDynamicSharedMemorySize, H_SMEM);
    cudaFuncSetAttribute(out_attn_kernel, cudaFuncAttributeMaxDynamicSharedMemorySize, 160000);
    cudaFuncSetAttribute(final_rows_kernel, cudaFuncAttributeMaxDynamicSharedMemorySize, 9 * C3 * 4);

    // fused weight transpose -> [6912, 768] fp16
    transpose_h<<<dim3(C3 / 32, DIMM / 32), 256>>>(Wq, p_Wh + (size_t)OQ * DIMM, DIMM, C3);
    transpose_h<<<dim3(C3 / 32, DIMM / 32), 256>>>(Wk, p_Wh + (size_t)OK * DIMM, DIMM, C3);
    transpose_h<<<dim3(C3 / 32, DIMM / 32), 256>>>(Wv, p_Wh + (size_t)OV * DIMM, DIMM, C3);
    transpose_h<<<dim3(DIMM / 32, C3 / 32), 256>>>(Wt, p_Wth, C3, DIMM);
    concat_bias<<<(C3X + 255) / 256, 256>>>(bq, bk, bv, p_bqkv);
    {
        int n4 = BB * SS * DIMM / 4;
        tohalf<<<(n4 + 255) / 256, 256>>>(x, p_xh, n4);
    }

    const int M1 = BB * SS;   // 12552
    {   // fused QKV: one launch, N = 6912
        dim3 grid(C3X / 128, M1PAD / 128);
        gemm_h1<<<grid, 256, H_SMEM>>>(p_xh, p_Wh, p_bqkv, p_qkv, M1, C3X, DIMM);
    }
    inter_cls_kernel<<<dim3(HH, BB), 256>>>();
    temporal_kernel<<<dim3(PP, HH, BB), 192>>>();

    const int M2 = BB * PP;   // 1560
    {
        int n4 = M2 * C3 / 4;
        tohalf<<<(n4 + 255) / 256, 256>>>(p_t1, p_t1h, n4);
        dim3 grid(DIMM / 128, M2PAD / 128);
        gemm_h1<<<grid, 256, H_SMEM>>>(p_t1h, p_Wth, bt, p_ti, M2, DIMM, C3);
    }
    {
        int n4 = M2 * DIMM / 4;
        tohalf<<<(n4 + 255) / 256, 256>>>(p_ti, p_tih, n4);
        dim3 grid(C3X / 128, M2PAD / 128);
        gemm_h1<<<grid, 256, H_SMEM>>>(p_tih, p_Wh, p_bqkv, p_q2kv, M2, C3X, DIMM);
    }
    {
        size_t smA = (size_t)(196 * 193 + 8 * D3 + 196) * 4;
        out_attn_kernel<<<dim3(1, HH, BB), 256, smA>>>(0, 196);
        size_t smB = (size_t)(8 * 193 + 8 * D3 + 8) * 4;
        out_attn_kernel<<<dim3(7, HH, BB), 256, smB>>>(1, 8);
    }
    final_rows_kernel<<<dim3(4, BB), 192, (size_t)9 * C3 * 4>>>(Wf, bf);
    {
        const size_t total4 = (size_t)BB * SS * DIMM / 4;
        bcast_kernel<<<(unsigned)((total4 + 255) / 256), 256>>>(out);
    }
}